// round 1
// baseline (speedup 1.0000x reference)
#include <cuda_runtime.h>
#include <cstdint>

#define H      2048
#define NSTEP  119
#define BATCH  16384

// Scratch (allocation-free rules: __device__ globals)
__device__ __align__(16) float    g_wt[8u * H * H];   // transposed weights, 128 MB
__device__ __align__(16) float    g_vec[2][2][H];     // [chain][0=p, 1=h]
__device__ __align__(16) float    g_ydot[2][NSTEP];   // per-step readout dots
__device__ unsigned               g_arrive;

// ---------------------------------------------------------------- init
__global__ void init_k(const float* __restrict__ pe, const float* __restrict__ ne) {
    int i = blockIdx.x * blockDim.x + threadIdx.x;
    if (i < H) { g_vec[0][0][i] = pe[i]; g_vec[1][0][i] = ne[i]; }
    if (i == 0) g_arrive = 0u;
}

// ---------------------------------------------------------------- transpose
// g_wt[z][j*H + i] = W_z[i*H + j];  z = chain*4 + phase,
// phase order per chain: W1[0], W2[0], W1[1], W2[1]
__global__ void transpose_k(const float* __restrict__ pW1, const float* __restrict__ pW2,
                            const float* __restrict__ nW1, const float* __restrict__ nW2) {
    __shared__ float tile[32][33];
    int z = blockIdx.z;
    int chain = z >> 2, ph = z & 3;
    const float* W1 = chain ? nW1 : pW1;
    const float* W2 = chain ? nW2 : pW2;
    const float* src = (ph == 0) ? W1
                     : (ph == 1) ? W2
                     : (ph == 2) ? W1 + (size_t)H * H
                                 : W2 + (size_t)H * H;
    float* dst = g_wt + (size_t)z * H * H;
    int j0 = blockIdx.x * 32, i0 = blockIdx.y * 32;
#pragma unroll
    for (int k = 0; k < 32; k += 8)
        tile[threadIdx.y + k][threadIdx.x] =
            src[(size_t)(i0 + threadIdx.y + k) * H + (j0 + threadIdx.x)];
    __syncthreads();
#pragma unroll
    for (int k = 0; k < 32; k += 8)
        dst[(size_t)(j0 + threadIdx.y + k) * H + (i0 + threadIdx.x)] =
            tile[threadIdx.x][threadIdx.y + k];
}

// ---------------------------------------------------------------- barrier
__device__ __forceinline__ void grid_barrier(unsigned target) {
    __syncthreads();
    if (threadIdx.x == 0) {
        __threadfence();
        unsigned prev = atomicAdd(&g_arrive, 1u);
        if (prev + 1u < target) {
            while (*(volatile unsigned*)&g_arrive < target) { }
            __threadfence();
        }
    }
    __syncthreads();
}

// ---------------------------------------------------------------- matvec core
// Each warp owns columns j = c0+warpid, c0+warpid+16, ... (full K range each).
template<bool RESID>
__device__ __forceinline__ void matvec_cols(
    const float* __restrict__ wmat, const float* __restrict__ bias,
    const float* __restrict__ sv,   float* __restrict__ odst,
    int c0, int c1, int warpid, int lane, float* pvals)
{
    const float4* v4 = (const float4*)sv;
    int slot = 0;
    for (int j = c0 + warpid; j < c1; j += 16, slot++) {
        const float4* w4 = (const float4*)(wmat + (size_t)j * H);
        float4 a = make_float4(0.f, 0.f, 0.f, 0.f);
#pragma unroll
        for (int it = 0; it < H / 128; it++) {
            float4 w = __ldg(w4 + it * 32 + lane);
            float4 v = v4[it * 32 + lane];
            a.x = fmaf(w.x, v.x, a.x);
            a.y = fmaf(w.y, v.y, a.y);
            a.z = fmaf(w.z, v.z, a.z);
            a.w = fmaf(w.w, v.w, a.w);
        }
        float s = (a.x + a.y) + (a.z + a.w);
#pragma unroll
        for (int off = 16; off; off >>= 1)
            s += __shfl_xor_sync(0xffffffffu, s, off);
        if (lane == 0) {
            float z = s + __ldg(bias + j);
            float act = z / (1.0f + expf(-z));          // silu
            if (RESID) { act += pvals[slot]; pvals[slot] = act; }
            __stcg(odst + j, act);
        }
    }
}

__device__ __forceinline__ float dot_sv_r(const float* __restrict__ sv,
                                          const float* __restrict__ rcol, int lane) {
    float4 a = make_float4(0.f, 0.f, 0.f, 0.f);
    const float4* v4 = (const float4*)sv;
    const float4* r4 = (const float4*)rcol;
#pragma unroll
    for (int it = 0; it < H / 128; it++) {
        float4 v = v4[it * 32 + lane];
        float4 r = __ldg(r4 + it * 32 + lane);
        a.x = fmaf(v.x, r.x, a.x);
        a.y = fmaf(v.y, r.y, a.y);
        a.z = fmaf(v.z, r.z, a.z);
        a.w = fmaf(v.w, r.w, a.w);
    }
    float s = (a.x + a.y) + (a.z + a.w);
#pragma unroll
    for (int off = 16; off; off >>= 1)
        s += __shfl_xor_sync(0xffffffffu, s, off);
    return s;
}

// ---------------------------------------------------------------- main
__global__ void __launch_bounds__(512, 1) rnn_main_k(
    const float* __restrict__ pb1, const float* __restrict__ pb2,
    const float* __restrict__ nb1, const float* __restrict__ nb2,
    const float* __restrict__ rW,  const float* __restrict__ rb,
    const int*   __restrict__ x,   float* __restrict__ out)
{
    __shared__ __align__(16) float sv[H];
    const int ncta = gridDim.x;
    const int half = ncta >> 1;
    const int chain = (blockIdx.x >= half) ? 1 : 0;
    const int cidx  = chain ? blockIdx.x - half : blockIdx.x;
    const int ccnt  = chain ? (ncta - half) : half;
    const int c0 = (int)((long long)cidx * H / ccnt);
    const int c1 = (int)((long long)(cidx + 1) * H / ccnt);
    const int lane = threadIdx.x & 31;
    const int warpid = threadIdx.x >> 5;

    const float* b1 = chain ? nb1 : pb1;
    const float* b2 = chain ? nb2 : pb2;
    const float* w0 = g_wt + (size_t)(chain * 4 + 0) * H * H;
    const float* w1 = g_wt + (size_t)(chain * 4 + 1) * H * H;
    const float* w2 = g_wt + (size_t)(chain * 4 + 2) * H * H;
    const float* w3 = g_wt + (size_t)(chain * 4 + 3) * H * H;
    float* p = g_vec[chain][0];
    float* h = g_vec[chain][1];
    const float* rcol = rW + chain * H;

    // register copies of this warp's residual-stream columns
    float pvals[8];
    {
        int slot = 0;
        for (int j = c0 + warpid; j < c1 && slot < 8; j += 16, slot++)
            pvals[slot] = __ldcg(p + j);
    }

    unsigned target = (unsigned)ncta;

    for (int step = 0; step < NSTEP; ++step) {
        // ---- phase 0: h = silu(p @ W1[0] + b1[0]) ----
        for (int idx = threadIdx.x; idx < H / 4; idx += blockDim.x)
            ((float4*)sv)[idx] = __ldcg((const float4*)p + idx);
        __syncthreads();
        if (step > 0 && cidx == 0 && warpid == 0) {     // ydot[step-1] = dot(p, r)
            float s = dot_sv_r(sv, rcol, lane);
            if (lane == 0) __stcg(&g_ydot[chain][step - 1], s);
        }
        matvec_cols<false>(w0, b1, sv, h, c0, c1, warpid, lane, pvals);
        grid_barrier(target); target += (unsigned)ncta;

        // ---- phase 1: p += silu(h @ W2[0] + b2[0]) ----
        for (int idx = threadIdx.x; idx < H / 4; idx += blockDim.x)
            ((float4*)sv)[idx] = __ldcg((const float4*)h + idx);
        __syncthreads();
        matvec_cols<true>(w1, b2, sv, p, c0, c1, warpid, lane, pvals);
        grid_barrier(target); target += (unsigned)ncta;

        // ---- phase 2: h = silu(p @ W1[1] + b1[1]) ----
        for (int idx = threadIdx.x; idx < H / 4; idx += blockDim.x)
            ((float4*)sv)[idx] = __ldcg((const float4*)p + idx);
        __syncthreads();
        matvec_cols<false>(w2, b1 + H, sv, h, c0, c1, warpid, lane, pvals);
        grid_barrier(target); target += (unsigned)ncta;

        // ---- phase 3: p += silu(h @ W2[1] + b2[1]) ----
        for (int idx = threadIdx.x; idx < H / 4; idx += blockDim.x)
            ((float4*)sv)[idx] = __ldcg((const float4*)h + idx);
        __syncthreads();
        matvec_cols<true>(w3, b2 + H, sv, p, c0, c1, warpid, lane, pvals);
        grid_barrier(target); target += (unsigned)ncta;
    }

    // last table row: ydot[NSTEP-1] = dot(p_final, r)
    if (cidx == 0 && warpid == 0) {
        float4 a = make_float4(0.f, 0.f, 0.f, 0.f);
        const float4* p4 = (const float4*)p;
        const float4* r4 = (const float4*)rcol;
#pragma unroll
        for (int it = 0; it < H / 128; it++) {
            float4 v = __ldcg(p4 + it * 32 + lane);
            float4 r = __ldg(r4 + it * 32 + lane);
            a.x = fmaf(v.x, r.x, a.x);
            a.y = fmaf(v.y, r.y, a.y);
            a.z = fmaf(v.z, r.z, a.z);
            a.w = fmaf(v.w, r.w, a.w);
        }
        float s = (a.x + a.y) + (a.z + a.w);
#pragma unroll
        for (int off = 16; off; off >>= 1)
            s += __shfl_xor_sync(0xffffffffu, s, off);
        if (lane == 0) __stcg(&g_ydot[chain][NSTEP - 1], s);
    }
    grid_barrier(target); target += (unsigned)ncta;

    // ---- readout: out[b] = sigmoid(ydot_p[x0] + ydot_n[x1] + rb) ----
    float rb0 = __ldg(rb);
    for (int b = blockIdx.x * blockDim.x + threadIdx.x; b < BATCH;
         b += ncta * blockDim.x) {
        int i0 = __ldg(&x[2 * b]);
        int i1 = __ldg(&x[2 * b + 1]);
        float z = __ldcg(&g_ydot[0][i0]) + __ldcg(&g_ydot[1][i1]) + rb0;
        out[b] = 1.0f / (1.0f + expf(-z));
    }
}

// ---------------------------------------------------------------- launch
extern "C" void kernel_launch(void* const* d_in, const int* in_sizes, int n_in,
                              void* d_out, int out_size) {
    const int*   x   = (const int*)d_in[0];
    const float* pe  = (const float*)d_in[1];
    const float* ne  = (const float*)d_in[2];
    const float* pW1 = (const float*)d_in[3];
    const float* pb1 = (const float*)d_in[4];
    const float* pW2 = (const float*)d_in[5];
    const float* pb2 = (const float*)d_in[6];
    const float* nW1 = (const float*)d_in[7];
    const float* nb1 = (const float*)d_in[8];
    const float* nW2 = (const float*)d_in[9];
    const float* nb2 = (const float*)d_in[10];
    const float* rW  = (const float*)d_in[11];
    const float* rb  = (const float*)d_in[12];
    float* out = (float*)d_out;

    int dev = 0;
    cudaGetDevice(&dev);
    int nsm = 148;
    cudaDeviceGetAttribute(&nsm, cudaDevAttrMultiProcessorCount, dev);
    if (nsm < 32)  nsm = 32;    // safety clamps (B200 = 148)
    if (nsm > 148) nsm = 148;   // 1 CTA/SM co-residency for the sw barrier

    init_k<<<(H + 255) / 256, 256>>>(pe, ne);
    transpose_k<<<dim3(H / 32, H / 32, 8), dim3(32, 8)>>>(pW1, pW2, nW1, nW2);
    rnn_main_k<<<nsm, 512>>>(pb1, pb2, nb1, nb2, rW, rb, x, out);
}

// round 4
// speedup vs baseline: 1.2927x; 1.2927x over previous
#include <cuda_runtime.h>
#include <cuda_fp16.h>
#include <cstdint>

#define H      2048
#define NSTEP  119
#define BATCH  16384
#define MAXCTA 80          // per chain

// ---------------- scratch (__device__ globals; no allocs allowed) ----------
__device__ __align__(16) __half g_wt[8u * H * H];     // fp16 transposed weights, 64 MB
__device__ __align__(16) float  g_vec[2][2][H];       // [chain][0=p, 1=h]
__device__ __align__(16) float  g_ydot[2][NSTEP];     // per-step readout dots
__device__ unsigned             g_flag[2][MAXCTA * 32];  // 128B-padded arrival flags
__device__ unsigned             g_rel[2][32];            // release words
__device__ unsigned             g_done;                  // final joint barrier

// ---------------------------------------------------------------- init
__global__ void init_k(const float* __restrict__ pe, const float* __restrict__ ne) {
    int i = blockIdx.x * blockDim.x + threadIdx.x;
    if (i < H) { g_vec[0][0][i] = pe[i]; g_vec[1][0][i] = ne[i]; }
    for (int k = i; k < 2 * MAXCTA * 32; k += gridDim.x * blockDim.x) {
        ((unsigned*)g_flag)[k] = 0u;
        if (k < 64) ((unsigned*)g_rel)[k] = 0u;
    }
    if (i == 0) g_done = 0u;
}

// ---------------------------------------------------------------- transpose+convert
// g_wt[z][j*H + i] = (half)W_z[i*H + j];  z = chain*4 + phase
__global__ void transpose_k(const float* __restrict__ pW1, const float* __restrict__ pW2,
                            const float* __restrict__ nW1, const float* __restrict__ nW2) {
    __shared__ float tile[32][33];
    int z = blockIdx.z;
    int chain = z >> 2, ph = z & 3;
    const float* W1 = chain ? nW1 : pW1;
    const float* W2 = chain ? nW2 : pW2;
    const float* src = (ph == 0) ? W1
                     : (ph == 1) ? W2
                     : (ph == 2) ? W1 + (size_t)H * H
                                 : W2 + (size_t)H * H;
    __half* dst = g_wt + (size_t)z * H * H;
    int j0 = blockIdx.x * 32, i0 = blockIdx.y * 32;
#pragma unroll
    for (int k = 0; k < 32; k += 8)
        tile[threadIdx.y + k][threadIdx.x] =
            src[(size_t)(i0 + threadIdx.y + k) * H + (j0 + threadIdx.x)];
    __syncthreads();
#pragma unroll
    for (int k = 0; k < 32; k += 8)
        dst[(size_t)(j0 + threadIdx.y + k) * H + (i0 + threadIdx.x)] =
            __float2half_rn(tile[threadIdx.x][threadIdx.y + k]);
}

// ---------------------------------------------------------------- per-chain barrier
// flag/release: arrivals are plain stores to padded words (no atomic serialization),
// collector (cidx==0) polls and releases. Per-chain domain. Spins back off with
// __nanosleep so 127 pollers don't saturate the L2 lines they are waiting on.
__device__ __forceinline__ void chain_barrier(int chain, int cidx, int ccnt, unsigned phase) {
    __syncthreads();
    if (cidx == 0) {
        if (threadIdx.x < 32) {
            bool all_in = false;
            while (!all_in) {
                bool mine = true;
                for (int b = 1 + (int)threadIdx.x; b < ccnt; b += 32)
                    if (*(volatile unsigned*)&g_flag[chain][b * 32] < phase) mine = false;
                all_in = __all_sync(0xffffffffu, mine);
                if (!all_in) __nanosleep(64);
            }
            __threadfence();
            if (threadIdx.x == 0)
                *(volatile unsigned*)&g_rel[chain][0] = phase;
        }
    } else if (threadIdx.x == 0) {
        __threadfence();
        *(volatile unsigned*)&g_flag[chain][cidx * 32] = phase;
        while (*(volatile unsigned*)&g_rel[chain][0] < phase) { __nanosleep(64); }
        __threadfence();
    }
    __syncthreads();
}

// ---------------------------------------------------------------- matvec core
// warp owns cols j = c0+warpid, +16, ... ; weights fp16, vector fp32 in smem.
template<bool RESID>
__device__ __forceinline__ void matvec_cols(
    const __half* __restrict__ wmat, const float* __restrict__ bias,
    const float* __restrict__ sv,    float* __restrict__ odst,
    int c0, int c1, int warpid, int lane, float* pvals)
{
    const float4* v4 = (const float4*)sv;
    int slot = 0;
    for (int j = c0 + warpid; j < c1; j += 16, slot++) {
        const uint2* w2p = (const uint2*)(wmat + (size_t)j * H);
        float4 a = make_float4(0.f, 0.f, 0.f, 0.f);
#pragma unroll
        for (int it = 0; it < H / 128; it++) {
            uint2 w = __ldg(w2p + it * 32 + lane);        // 4 halves
            float2 f0 = __half22float2(*(__half2*)&w.x);
            float2 f1 = __half22float2(*(__half2*)&w.y);
            float4 v = v4[it * 32 + lane];                // conflict-free LDS.128
            a.x = fmaf(f0.x, v.x, a.x);
            a.y = fmaf(f0.y, v.y, a.y);
            a.z = fmaf(f1.x, v.z, a.z);
            a.w = fmaf(f1.y, v.w, a.w);
        }
        float s = (a.x + a.y) + (a.z + a.w);
#pragma unroll
        for (int off = 16; off; off >>= 1)
            s += __shfl_xor_sync(0xffffffffu, s, off);
        if (lane == 0) {
            float z = s + __ldg(bias + j);
            float act = z / (1.0f + expf(-z));            // silu
            if (RESID) { act += pvals[slot]; pvals[slot] = act; }
            __stcg(odst + j, act);
        }
    }
}

__device__ __forceinline__ float dot_sv_r(const float* __restrict__ sv,
                                          const float* __restrict__ rcol, int lane) {
    float4 a = make_float4(0.f, 0.f, 0.f, 0.f);
    const float4* v4 = (const float4*)sv;
    const float4* r4 = (const float4*)rcol;
#pragma unroll
    for (int it = 0; it < H / 128; it++) {
        float4 v = v4[it * 32 + lane];
        float4 r = __ldg(r4 + it * 32 + lane);
        a.x = fmaf(v.x, r.x, a.x);
        a.y = fmaf(v.y, r.y, a.y);
        a.z = fmaf(v.z, r.z, a.z);
        a.w = fmaf(v.w, r.w, a.w);
    }
    float s = (a.x + a.y) + (a.z + a.w);
#pragma unroll
    for (int off = 16; off; off >>= 1)
        s += __shfl_xor_sync(0xffffffffu, s, off);
    return s;
}

// ---------------------------------------------------------------- main
__global__ void __launch_bounds__(512, 1) rnn_main_k(
    const float* __restrict__ pb1, const float* __restrict__ pb2,
    const float* __restrict__ nb1, const float* __restrict__ nb2,
    const float* __restrict__ rW,  const float* __restrict__ rb,
    const int*   __restrict__ x,   float* __restrict__ out)
{
    __shared__ __align__(16) float sv[H];
    const int ncta = gridDim.x;
    const int half = ncta >> 1;
    const int chain = (blockIdx.x >= half) ? 1 : 0;
    const int cidx  = chain ? blockIdx.x - half : blockIdx.x;
    const int ccnt  = chain ? (ncta - half) : half;
    const int c0 = (int)((long long)cidx * H / ccnt);
    const int c1 = (int)((long long)(cidx + 1) * H / ccnt);
    const int lane = threadIdx.x & 31;
    const int warpid = threadIdx.x >> 5;
    const bool is_ydot_cta = (cidx == ccnt - 1);   // keep collector (cidx 0) lean

    const float* b1 = chain ? nb1 : pb1;
    const float* b2 = chain ? nb2 : pb2;
    const __half* w0 = g_wt + (size_t)(chain * 4 + 0) * H * H;
    const __half* w1 = g_wt + (size_t)(chain * 4 + 1) * H * H;
    const __half* w2 = g_wt + (size_t)(chain * 4 + 2) * H * H;
    const __half* w3 = g_wt + (size_t)(chain * 4 + 3) * H * H;
    float* p = g_vec[chain][0];
    float* h = g_vec[chain][1];
    const float* rcol = rW + chain * H;

    // register copies of this warp's residual-stream columns (fixed assignment)
    float pvals[4];
    {
        int slot = 0;
        for (int j = c0 + warpid; j < c1 && slot < 4; j += 16, slot++)
            pvals[slot] = __ldcg(p + j);
    }

    unsigned phase = 1u;

    for (int step = 0; step < NSTEP; ++step) {
        // ---- phase 0: h = silu(p @ W1[0] + b1[0]) ----
        for (int idx = threadIdx.x; idx < H / 4; idx += blockDim.x)
            ((float4*)sv)[idx] = __ldcg((const float4*)p + idx);
        __syncthreads();
        if (step > 0 && is_ydot_cta && warpid == 0) {     // ydot[step-1] = dot(p, r)
            float s = dot_sv_r(sv, rcol, lane);
            if (lane == 0) __stcg(&g_ydot[chain][step - 1], s);
        }
        matvec_cols<false>(w0, b1, sv, h, c0, c1, warpid, lane, pvals);
        chain_barrier(chain, cidx, ccnt, phase++);

        // ---- phase 1: p += silu(h @ W2[0] + b2[0]) ----
        for (int idx = threadIdx.x; idx < H / 4; idx += blockDim.x)
            ((float4*)sv)[idx] = __ldcg((const float4*)h + idx);
        __syncthreads();
        matvec_cols<true>(w1, b2, sv, p, c0, c1, warpid, lane, pvals);
        chain_barrier(chain, cidx, ccnt, phase++);

        // ---- phase 2: h = silu(p @ W1[1] + b1[1]) ----
        for (int idx = threadIdx.x; idx < H / 4; idx += blockDim.x)
            ((float4*)sv)[idx] = __ldcg((const float4*)p + idx);
        __syncthreads();
        matvec_cols<false>(w2, b1 + H, sv, h, c0, c1, warpid, lane, pvals);
        chain_barrier(chain, cidx, ccnt, phase++);

        // ---- phase 3: p += silu(h @ W2[1] + b2[1]) ----
        for (int idx = threadIdx.x; idx < H / 4; idx += blockDim.x)
            ((float4*)sv)[idx] = __ldcg((const float4*)h + idx);
        __syncthreads();
        matvec_cols<true>(w3, b2 + H, sv, p, c0, c1, warpid, lane, pvals);
        chain_barrier(chain, cidx, ccnt, phase++);
    }

    // last table row: ydot[NSTEP-1] = dot(p_final, r)
    if (is_ydot_cta && warpid == 0) {
        float4 a = make_float4(0.f, 0.f, 0.f, 0.f);
        const float4* p4 = (const float4*)p;
        const float4* r4 = (const float4*)rcol;
#pragma unroll
        for (int it = 0; it < H / 128; it++) {
            float4 v = __ldcg(p4 + it * 32 + lane);
            float4 r = __ldg(r4 + it * 32 + lane);
            a.x = fmaf(v.x, r.x, a.x);
            a.y = fmaf(v.y, r.y, a.y);
            a.z = fmaf(v.z, r.z, a.z);
            a.w = fmaf(v.w, r.w, a.w);
        }
        float s = (a.x + a.y) + (a.z + a.w);
#pragma unroll
        for (int off = 16; off; off >>= 1)
            s += __shfl_xor_sync(0xffffffffu, s, off);
        if (lane == 0) __stcg(&g_ydot[chain][NSTEP - 1], s);
    }

    // ---- joint barrier (both chains) before readout ----
    __syncthreads();
    if (threadIdx.x == 0) {
        __threadfence();
        atomicAdd(&g_done, 1u);
        while (*(volatile unsigned*)&g_done < (unsigned)ncta) { __nanosleep(64); }
        __threadfence();
    }
    __syncthreads();

    // ---- readout: out[b] = sigmoid(ydot_p[x0] + ydot_n[x1] + rb) ----
    float rb0 = __ldg(rb);
    for (int b = blockIdx.x * blockDim.x + threadIdx.x; b < BATCH;
         b += ncta * blockDim.x) {
        int i0 = __ldg(&x[2 * b]);
        int i1 = __ldg(&x[2 * b + 1]);
        float z = __ldcg(&g_ydot[0][i0]) + __ldcg(&g_ydot[1][i1]) + rb0;
        out[b] = 1.0f / (1.0f + expf(-z));
    }
}

// ---------------------------------------------------------------- launch
extern "C" void kernel_launch(void* const* d_in, const int* in_sizes, int n_in,
                              void* d_out, int out_size) {
    const int*   x   = (const int*)d_in[0];
    const float* pe  = (const float*)d_in[1];
    const float* ne  = (const float*)d_in[2];
    const float* pW1 = (const float*)d_in[3];
    const float* pb1 = (const float*)d_in[4];
    const float* pW2 = (const float*)d_in[5];
    const float* pb2 = (const float*)d_in[6];
    const float* nW1 = (const float*)d_in[7];
    const float* nb1 = (const float*)d_in[8];
    const float* nW2 = (const float*)d_in[9];
    const float* nb2 = (const float*)d_in[10];
    const float* rW  = (const float*)d_in[11];
    const float* rb  = (const float*)d_in[12];
    float* out = (float*)d_out;

    int dev = 0;
    cudaGetDevice(&dev);
    int nsm = 148;
    cudaDeviceGetAttribute(&nsm, cudaDevAttrMultiProcessorCount, dev);

    // Ensure the persistent-barrier kernel is fully co-resident.
    int per_sm = 1;
    cudaOccupancyMaxActiveBlocksPerMultiprocessor(&per_sm, rnn_main_k, 512, sizeof(float) * H);
    if (per_sm < 1) per_sm = 1;
    int maxcta = nsm * per_sm;

    // 128 CTAs (64/chain) -> 2048 cols / 64 CTAs = 32/CTA = exactly 2 cols/warp
    int ncta = 128;
    if (ncta > maxcta) ncta = maxcta & ~1;   // must all be resident; even count
    if (ncta > 2 * MAXCTA) ncta = 2 * MAXCTA;
    if (ncta < 2)   ncta = 2;

    init_k<<<8, 256>>>(pe, ne);
    transpose_k<<<dim3(H / 32, H / 32, 8), dim3(32, 8)>>>(pW1, pW2, nW1, nW2);
    rnn_main_k<<<ncta, 512>>>(pb1, pb2, nb1, nb2, rW, rb, x, out);
}